// round 7
// baseline (speedup 1.0000x reference)
#include <cuda_runtime.h>
#include <cuda_bf16.h>
#include <cstdint>

// Problem constants
constexpr int NROWS = 16384;
constexpr int DIM   = 128;
constexpr int TOPK  = 32;
constexpr int SLAB  = 2048;
constexpr int NSLABS = NROWS / SLAB;          // 8
constexpr long long NKTOT = (long long)NROWS * TOPK;

constexpr int KCAT = 384;                     // 3 x 128 (hi|lo|hi vs hi|hi|lo)
constexpr int KCHUNK = 192;                   // K processed per smem residency
constexpr int NCHUNK = KCAT / KCHUNK;         // 2
constexpr int KSTEPS = KCHUNK / 16;           // 12 per chunk

// scratch (sanctioned __device__ globals)
__device__ __align__(128) __nv_bfloat16 g_scratch[(size_t)SLAB * NROWS];      // 64 MB
__device__ __align__(128) __nv_bfloat16 g_Acat[(size_t)NROWS * KCAT];         // 12 MB
__device__ __align__(128) __nv_bfloat16 g_Bcat[(size_t)NROWS * KCAT];         // 12 MB

// ---------------- prep: build split operand tables ----------------
__global__ __launch_bounds__(256) void prep_kernel(const float* __restrict__ W) {
    int t = blockIdx.x * 256 + threadIdx.x;
    if (t >= NROWS * DIM) return;
    int row = t >> 7, j = t & 127;
    float w = W[t];
    __nv_bfloat16 hi = __float2bfloat16(w);
    float r = w - __bfloat162float(hi);
    __nv_bfloat16 lo = __float2bfloat16(r);
    size_t base = (size_t)row * KCAT;
    g_Acat[base + j]       = hi;
    g_Acat[base + 128 + j] = lo;
    g_Acat[base + 256 + j] = hi;
    g_Bcat[base + j]       = hi;
    g_Bcat[base + 128 + j] = hi;
    g_Bcat[base + 256 + j] = lo;
}

// ---------------- HMMA GEMM: 128x128 tile/CTA, K chunked 2x192 ----------------
constexpr int SAC = 200;                      // bf16/row incl pad (400 B)
constexpr int TILE_B = 128 * SAC * 2;         // 51200 B per tile
constexpr int GEMM_SMEM = 2 * TILE_B;         // 102400 -> 2 CTAs/SM

__device__ __forceinline__ uint32_t smem_u32(const void* p) {
    uint32_t a;
    asm("{ .reg .u64 t; cvta.to.shared.u64 t, %1; cvt.u32.u64 %0, t; }" : "=r"(a) : "l"(p));
    return a;
}
__device__ __forceinline__ void ldm_x4(uint32_t* r, uint32_t addr) {
    asm volatile("ldmatrix.sync.aligned.m8n8.x4.shared.b16 {%0,%1,%2,%3}, [%4];"
                 : "=r"(r[0]), "=r"(r[1]), "=r"(r[2]), "=r"(r[3]) : "r"(addr));
}
__device__ __forceinline__ void mma16816(float* c, const uint32_t* a, const uint32_t* b) {
    asm volatile(
        "mma.sync.aligned.m16n8k16.row.col.f32.bf16.bf16.f32 "
        "{%0,%1,%2,%3}, {%4,%5,%6,%7}, {%8,%9}, {%0,%1,%2,%3};"
        : "+f"(c[0]), "+f"(c[1]), "+f"(c[2]), "+f"(c[3])
        : "r"(a[0]), "r"(a[1]), "r"(a[2]), "r"(a[3]), "r"(b[0]), "r"(b[1]));
}

__global__ __launch_bounds__(256, 2) void gemm_kernel(int rowBase) {
    extern __shared__ __nv_bfloat16 sm[];
    __nv_bfloat16* As = sm;                   // [128][SAC]
    __nv_bfloat16* Bs = sm + 128 * SAC;

    const int tid  = threadIdx.x;
    const int lane = tid & 31, w = tid >> 5;
    const int wm = w >> 2, wn = w & 3;        // warp grid 2x4, warp tile 64x32
    const int g = lane >> 2, tig = lane & 3;
    const int rowA0 = rowBase + blockIdx.y * 128;
    const int rowB0 = blockIdx.x * 128;

    const uint32_t sbase = smem_u32(sm);
    // ldmatrix lane addresses (bytes), chunk-invariant parts
    uint32_t addrA[4], addrB[2];
#pragma unroll
    for (int mi = 0; mi < 4; ++mi)
        addrA[mi] = sbase + (uint32_t)((wm * 64 + mi * 16 + (lane & 15)) * 400 + (lane >> 4) * 16);
    const uint32_t grp = lane >> 3;
#pragma unroll
    for (int p = 0; p < 2; ++p)
        addrB[p] = sbase + (uint32_t)TILE_B +
                   (uint32_t)((wn * 32 + p * 16 + (grp >> 1) * 8 + (lane & 7)) * 400 + (grp & 1) * 16);

    float acc[4][4][4];
#pragma unroll
    for (int mi = 0; mi < 4; ++mi)
#pragma unroll
        for (int ni = 0; ni < 4; ++ni)
#pragma unroll
            for (int e = 0; e < 4; ++e) acc[mi][ni][e] = 0.f;

    const char* Ag = (const char*)g_Acat + (size_t)rowA0 * 768;
    const char* Bg = (const char*)g_Bcat + (size_t)rowB0 * 768;

    for (int ch = 0; ch < NCHUNK; ++ch) {
        if (ch) __syncthreads();
        // load chunk: 128 rows x 384 B per tile (24 x 16B chunks per row)
#pragma unroll
        for (int it = 0; it < 12; ++it) {
            int i = tid + it * 256;           // 0..3071
            int r = i / 24, c = i % 24;
            uint4 va = *(const uint4*)(Ag + (size_t)r * 768 + ch * 384 + c * 16);
            uint4 vb = *(const uint4*)(Bg + (size_t)r * 768 + ch * 384 + c * 16);
            *(uint4*)((char*)As + r * 400 + c * 16) = va;
            *(uint4*)((char*)Bs + r * 400 + c * 16) = vb;
        }
        __syncthreads();

#pragma unroll 4
        for (int k = 0; k < KSTEPS; ++k) {
            const uint32_t koff = (uint32_t)(k * 32);   // 16 bf16
            uint32_t af[4][4], bf[2][4];
#pragma unroll
            for (int mi = 0; mi < 4; ++mi) ldm_x4(af[mi], addrA[mi] + koff);
#pragma unroll
            for (int p = 0; p < 2; ++p)    ldm_x4(bf[p],  addrB[p] + koff);
#pragma unroll
            for (int mi = 0; mi < 4; ++mi)
#pragma unroll
                for (int ni = 0; ni < 4; ++ni)
                    mma16816(acc[mi][ni], af[mi], bf[ni >> 1] + (ni & 1) * 2);
        }
    }
    __syncthreads();

    // stage accumulators as bf16 (stride 136 bf16), then coalesced copy out
    __nv_bfloat16* st = sm;
#pragma unroll
    for (int mi = 0; mi < 4; ++mi)
#pragma unroll
        for (int ni = 0; ni < 4; ++ni) {
            int r0 = wm * 64 + mi * 16 + g;
            int c0 = wn * 32 + ni * 8 + tig * 2;
            __nv_bfloat162 lo = __float22bfloat162_rn(make_float2(acc[mi][ni][0], acc[mi][ni][1]));
            __nv_bfloat162 hi = __float22bfloat162_rn(make_float2(acc[mi][ni][2], acc[mi][ni][3]));
            *(__nv_bfloat162*)(st + r0 * 136 + c0)       = lo;
            *(__nv_bfloat162*)(st + (r0 + 8) * 136 + c0) = hi;
        }
    __syncthreads();

    __nv_bfloat16* outp = g_scratch + (size_t)(blockIdx.y * 128) * NROWS + rowB0;
#pragma unroll
    for (int it = 0; it < 8; ++it) {
        int i = tid + it * 256;               // 0..2047 (128 rows x 16 uint4)
        int r = i >> 4, c = i & 15;
        uint4 v = *(const uint4*)(st + r * 136 + c * 8);
        *(uint4*)(outp + (size_t)r * NROWS + c * 8) = v;
    }
}

// ---------------- select: pivot prefilter (bf16 approx) + exact fp32 re-rank ----------------
__device__ __forceinline__ unsigned f2key(float f) {
    unsigned u = __float_as_uint(f);
    return u ^ (unsigned)((((int)u) >> 31) | 0x80000000);
}

constexpr int CAND_CAP = 1024;
constexpr float DELTA = 0.5f;   // >> bf16-scratch (0.065) + split-GEMM (0.012) error bounds

__global__ __launch_bounds__(512) void select_kernel(const float* __restrict__ W,
                                                     float* __restrict__ out,
                                                     int rowBase) {
    __shared__ unsigned candI[CAND_CAP];
    __shared__ unsigned candK[CAND_CAP];
    __shared__ float    candV[CAND_CAP];
    __shared__ unsigned flags[CAND_CAP];
    __shared__ float sWrow[128];
    __shared__ float sWarp2[16];
    __shared__ float sThr;
    __shared__ unsigned sCnt;

    const int tid = threadIdx.x;
    const int lane = tid & 31, warp = tid >> 5;
    const int row_local = blockIdx.x;
    const int row = rowBase + row_local;

    if (tid == 0) sCnt = 0;
    if (tid < 32) {
        float4 wv = *((const float4*)(W + (size_t)row * DIM) + tid);
        *((float4*)sWrow + tid) = wv;
    }

    // load 32 contiguous bf16 approx values (4 x uint4 = 64 B)
    const uint4* rp = (const uint4*)(g_scratch + (size_t)row_local * NROWS) + tid * 4;
    uint4 qu[4];
#pragma unroll
    for (int i = 0; i < 4; ++i) qu[i] = rp[i];
    float qv[32];
#pragma unroll
    for (int i = 0; i < 4; ++i) {
        const unsigned wds[4] = {qu[i].x, qu[i].y, qu[i].z, qu[i].w};
#pragma unroll
        for (int j = 0; j < 4; ++j) {
            float2 f = __bfloat1622float2(*(const __nv_bfloat162*)&wds[j]);
            qv[i * 8 + j * 2]     = f.x;
            qv[i * 8 + j * 2 + 1] = f.y;
        }
    }

    // phase 1: per-thread top-2, warp merge, block-min of warp 2nd-max
    float m1 = -3.4e38f, m2 = -3.4e38f;
#pragma unroll
    for (int i = 0; i < 32; ++i) {
        float v = qv[i];
        if (v > m1) { m2 = m1; m1 = v; }
        else if (v > m2) m2 = v;
    }
#pragma unroll
    for (int off = 16; off > 0; off >>= 1) {
        float o1 = __shfl_down_sync(0xffffffffu, m1, off);
        float o2 = __shfl_down_sync(0xffffffffu, m2, off);
        float n1 = m1 > o1 ? m1 : o1;
        float n2 = (m1 > o1) ? (m2 > o1 ? m2 : o1) : (o2 > m1 ? o2 : m1);
        m1 = n1; m2 = n2;
    }
    if (lane == 0) sWarp2[warp] = m2;
    __syncthreads();
    if (warp == 0) {
        float v = (lane < 16) ? sWarp2[lane] : 3.4e38f;
#pragma unroll
        for (int off = 8; off > 0; off >>= 1) {
            float o = __shfl_down_sync(0xffffffffu, v, off);
            v = o < v ? o : v;
        }
        if (lane == 0) sThr = v - DELTA;
    }
    __syncthreads();
    const float thr = sThr;

    // phase 2: compact candidate indices
#pragma unroll
    for (int i = 0; i < 32; ++i) {
        if (qv[i] >= thr) {
            unsigned p = atomicAdd(&sCnt, 1u);
            if (p < CAND_CAP) candI[p] = (unsigned)(tid * 32 + i);
        }
    }
    __syncthreads();
    const int C = (int)(sCnt < CAND_CAP ? sCnt : CAND_CAP);

    // phase 3: exact fp32 dot per candidate
    for (int b = 0; b < C; b += 512) {
        int ci = b + tid;
        if (ci < C) {
            const float4* wc = (const float4*)(W + (size_t)candI[ci] * DIM);
            float4 acc4 = make_float4(0.f, 0.f, 0.f, 0.f);
#pragma unroll
            for (int j = 0; j < 32; ++j) {
                float4 a = *((const float4*)sWrow + j);
                float4 bb = __ldg(wc + j);
                acc4.x = fmaf(a.x, bb.x, acc4.x);
                acc4.y = fmaf(a.y, bb.y, acc4.y);
                acc4.z = fmaf(a.z, bb.z, acc4.z);
                acc4.w = fmaf(a.w, bb.w, acc4.w);
            }
            float dot = (acc4.x + acc4.y) + (acc4.z + acc4.w);
            candV[ci] = dot;
            candK[ci] = f2key(dot);
        }
    }
    __syncthreads();

    // phase 4: exact rank (val desc, idx asc)
    for (int b = 0; b < C; b += 512) {
        int ci = b + tid;
        if (ci < C) {
            unsigned myk = candK[ci], myi = candI[ci];
            int rank = 0;
            for (int j = 0; j < C; ++j) {
                unsigned kj = candK[j];
                rank += (kj > myk) || (kj == myk && candI[j] < myi);
            }
            flags[ci] = (rank < TOPK) ? 1u : 0u;
        }
    }
    __syncthreads();

    // phase 5: column-sorted emit
    for (int b = 0; b < C; b += 512) {
        int ci = b + tid;
        if (ci < C && flags[ci]) {
            unsigned myi = candI[ci];
            int pos = 0;
            for (int j = 0; j < C; ++j)
                pos += (flags[j] && candI[j] < myi);
            const long long o = (long long)row * TOPK + pos;
            out[o]             = (float)row;
            out[NKTOT + o]     = (float)myi;
            out[2 * NKTOT + o] = candV[ci];
        }
    }
}

// ---------------- launch ----------------
extern "C" void kernel_launch(void* const* d_in, const int* in_sizes, int n_in,
                              void* d_out, int out_size) {
    const float* W = (const float*)d_in[n_in > 1 ? 1 : 0];
    if (in_sizes[0] == NROWS * DIM) W = (const float*)d_in[0];
    float* out = (float*)d_out;

    cudaFuncSetAttribute(gemm_kernel,
                         cudaFuncAttributeMaxDynamicSharedMemorySize, GEMM_SMEM);

    prep_kernel<<<(NROWS * DIM + 255) / 256, 256>>>(W);
    for (int s = 0; s < NSLABS; ++s) {
        gemm_kernel<<<dim3(NROWS / 128, SLAB / 128), 256, GEMM_SMEM>>>(s * SLAB);
        select_kernel<<<SLAB, 512>>>(W, out, s * SLAB);
    }
}

// round 8
// speedup vs baseline: 1.3212x; 1.3212x over previous
#include <cuda_runtime.h>
#include <cuda_bf16.h>
#include <cstdint>

// Problem constants
constexpr int NROWS = 16384;
constexpr int DIM   = 128;
constexpr int TOPK  = 32;
constexpr int SLAB  = 1024;
constexpr int NSLABS = NROWS / SLAB;          // 16
constexpr long long NKTOT = (long long)NROWS * TOPK;

constexpr int KCAT = 384;                     // 3 x 128 (hi|lo|hi vs hi|hi|lo)
constexpr int NKSTEP = KCAT / 16;             // 24 k-steps

// scratch (sanctioned __device__ globals)
__device__ __align__(128) float g_scratch[(size_t)SLAB * NROWS];              // 64 MB
__device__ __align__(128) __nv_bfloat16 g_Acat[(size_t)NROWS * KCAT];         // 12 MB
__device__ __align__(128) __nv_bfloat16 g_Bcat[(size_t)NROWS * KCAT];         // 12 MB

// ---------------- prep: build split operand tables ----------------
__global__ __launch_bounds__(256) void prep_kernel(const float* __restrict__ W) {
    int t = blockIdx.x * 256 + threadIdx.x;
    if (t >= NROWS * DIM) return;
    int row = t >> 7, j = t & 127;
    float w = W[t];
    __nv_bfloat16 hi = __float2bfloat16(w);
    float r = w - __bfloat162float(hi);
    __nv_bfloat16 lo = __float2bfloat16(r);
    size_t base = (size_t)row * KCAT;
    g_Acat[base + j]       = hi;
    g_Acat[base + 128 + j] = lo;
    g_Acat[base + 256 + j] = hi;
    g_Bcat[base + j]       = hi;
    g_Bcat[base + 128 + j] = hi;
    g_Bcat[base + 256 + j] = lo;
}

// ---------------- HMMA GEMM: 128x128 tile/CTA, K=384 resident, 512 threads ----------------
constexpr int SAC = 392;                      // bf16 per smem row incl pad -> 784 B stride
constexpr int TILE_B = 128 * SAC * 2;         // 100352 B per tile
constexpr int GEMM_SMEM = 2 * TILE_B;         // 200704 -> 1 CTA/SM

__device__ __forceinline__ uint32_t smem_u32(const void* p) {
    uint32_t a;
    asm("{ .reg .u64 t; cvta.to.shared.u64 t, %1; cvt.u32.u64 %0, t; }" : "=r"(a) : "l"(p));
    return a;
}
__device__ __forceinline__ void ldm_x4(uint32_t* r, uint32_t addr) {
    asm volatile("ldmatrix.sync.aligned.m8n8.x4.shared.b16 {%0,%1,%2,%3}, [%4];"
                 : "=r"(r[0]), "=r"(r[1]), "=r"(r[2]), "=r"(r[3]) : "r"(addr));
}
__device__ __forceinline__ void mma16816(float* c, const uint32_t* a, const uint32_t* b) {
    asm volatile(
        "mma.sync.aligned.m16n8k16.row.col.f32.bf16.bf16.f32 "
        "{%0,%1,%2,%3}, {%4,%5,%6,%7}, {%8,%9}, {%0,%1,%2,%3};"
        : "+f"(c[0]), "+f"(c[1]), "+f"(c[2]), "+f"(c[3])
        : "r"(a[0]), "r"(a[1]), "r"(a[2]), "r"(a[3]), "r"(b[0]), "r"(b[1]));
}

__global__ __launch_bounds__(512, 1) void gemm_kernel(int rowBase) {
    extern __shared__ __nv_bfloat16 sm[];
    __nv_bfloat16* As = sm;                   // [128][SAC]
    __nv_bfloat16* Bs = sm + 128 * SAC;

    const int tid  = threadIdx.x;
    const int lane = tid & 31, w = tid >> 5;
    const int wm = w >> 2, wn = w & 3;        // warp grid 4x4, warp tile 32x32
    const int g = lane >> 2, tig = lane & 3;
    const int rowA0 = rowBase + blockIdx.y * 128;
    const int rowB0 = blockIdx.x * 128;

    const uint32_t sbase = smem_u32(sm);
    // ldmatrix lane addresses (validated in R7): A m16-frags, B n16-frags
    uint32_t addrA[2], addrB[2];
#pragma unroll
    for (int mi = 0; mi < 2; ++mi)
        addrA[mi] = sbase + (uint32_t)((wm * 32 + mi * 16 + (lane & 15)) * 784 + (lane >> 4) * 16);
    const uint32_t grp = lane >> 3;
#pragma unroll
    for (int p = 0; p < 2; ++p)
        addrB[p] = sbase + (uint32_t)TILE_B +
                   (uint32_t)((wn * 32 + p * 16 + (grp >> 1) * 8 + (lane & 7)) * 784 + (grp & 1) * 16);

    // ---- load tiles: 128 rows x 48 16B-chunks each (coalesced gmem, sequential smem)
    const char* Ag = (const char*)g_Acat + (size_t)rowA0 * 768;
    const char* Bg = (const char*)g_Bcat + (size_t)rowB0 * 768;
#pragma unroll
    for (int it = 0; it < 12; ++it) {
        int i = tid + it * 512;               // 0..6143
        int r = i / 48, c = i % 48;
        uint4 va = *(const uint4*)(Ag + (size_t)r * 768 + c * 16);
        uint4 vb = *(const uint4*)(Bg + (size_t)r * 768 + c * 16);
        *(uint4*)((char*)As + r * 784 + c * 16) = va;
        *(uint4*)((char*)Bs + r * 784 + c * 16) = vb;
    }
    __syncthreads();

    // ---- mainloop: 24 k-steps, per warp 2x4 mma frags (32x32)
    float acc[2][4][4];
#pragma unroll
    for (int mi = 0; mi < 2; ++mi)
#pragma unroll
        for (int ni = 0; ni < 4; ++ni)
#pragma unroll
            for (int e = 0; e < 4; ++e) acc[mi][ni][e] = 0.f;

#pragma unroll 4
    for (int k = 0; k < NKSTEP; ++k) {
        const uint32_t koff = (uint32_t)(k * 32);     // 16 bf16
        uint32_t af[2][4], bf[2][4];
#pragma unroll
        for (int mi = 0; mi < 2; ++mi) ldm_x4(af[mi], addrA[mi] + koff);
#pragma unroll
        for (int p = 0; p < 2; ++p)    ldm_x4(bf[p],  addrB[p] + koff);
#pragma unroll
        for (int mi = 0; mi < 2; ++mi)
#pragma unroll
            for (int ni = 0; ni < 4; ++ni)
                mma16816(acc[mi][ni], af[mi], bf[ni >> 1] + (ni & 1) * 2);
    }
    __syncthreads();

    // ---- stage accumulators to smem (fp32, stride 132), then coalesced copy out
    float* st = (float*)sm;
#pragma unroll
    for (int mi = 0; mi < 2; ++mi)
#pragma unroll
        for (int ni = 0; ni < 4; ++ni) {
            int r0 = wm * 32 + mi * 16 + g;
            int c0 = wn * 32 + ni * 8 + tig * 2;
            *(float2*)(st + r0 * 132 + c0)       = make_float2(acc[mi][ni][0], acc[mi][ni][1]);
            *(float2*)(st + (r0 + 8) * 132 + c0) = make_float2(acc[mi][ni][2], acc[mi][ni][3]);
        }
    __syncthreads();

    float* outp = g_scratch + (size_t)(blockIdx.y * 128) * NROWS + rowB0;
#pragma unroll
    for (int it = 0; it < 8; ++it) {
        int i = tid + it * 512;               // 0..4095 float4 slots
        int r = i >> 5, c4 = i & 31;
        float4 v = *(const float4*)(st + r * 132 + c4 * 4);
        *(float4*)(outp + (size_t)r * NROWS + c4 * 4) = v;
    }
}

// ---------------- select: pivot prefilter (approx) + exact fp32 re-rank (R6-proven) ----------------
__device__ __forceinline__ unsigned f2key(float f) {
    unsigned u = __float_as_uint(f);
    return u ^ (unsigned)((((int)u) >> 31) | 0x80000000);
}

constexpr int CAND_CAP = 1024;
constexpr float DELTA = 0.05f;   // guard band >> split-GEMM error (~0.012)

__global__ __launch_bounds__(512) void select_kernel(const float* __restrict__ W,
                                                     float* __restrict__ out,
                                                     int rowBase) {
    __shared__ unsigned candI[CAND_CAP];
    __shared__ unsigned candK[CAND_CAP];
    __shared__ float    candV[CAND_CAP];
    __shared__ unsigned flags[CAND_CAP];
    __shared__ float sWrow[128];
    __shared__ float sWarp2[16];
    __shared__ float sThr;
    __shared__ unsigned sCnt;

    const int tid = threadIdx.x;
    const int lane = tid & 31, warp = tid >> 5;
    const int row_local = blockIdx.x;
    const int row = rowBase + row_local;

    if (tid == 0) sCnt = 0;
    if (tid < 32) {
        float4 wv = *((const float4*)(W + (size_t)row * DIM) + tid);
        *((float4*)sWrow + tid) = wv;
    }

    const float4* rp = (const float4*)(g_scratch + (size_t)row_local * NROWS) + tid * 8;
    float4 q[8];
#pragma unroll
    for (int i = 0; i < 8; ++i) q[i] = rp[i];

    // phase 1: per-thread top-2, warp merge, block-min of warp 2nd-max
    float m1 = -3.4e38f, m2 = -3.4e38f;
#pragma unroll
    for (int i = 0; i < 8; ++i) {
        float vv[4] = {q[i].x, q[i].y, q[i].z, q[i].w};
#pragma unroll
        for (int e = 0; e < 4; ++e) {
            float v = vv[e];
            if (v > m1) { m2 = m1; m1 = v; }
            else if (v > m2) m2 = v;
        }
    }
#pragma unroll
    for (int off = 16; off > 0; off >>= 1) {
        float o1 = __shfl_down_sync(0xffffffffu, m1, off);
        float o2 = __shfl_down_sync(0xffffffffu, m2, off);
        float n1 = m1 > o1 ? m1 : o1;
        float n2 = (m1 > o1) ? (m2 > o1 ? m2 : o1) : (o2 > m1 ? o2 : m1);
        m1 = n1; m2 = n2;
    }
    if (lane == 0) sWarp2[warp] = m2;
    __syncthreads();
    if (warp == 0) {
        float v = (lane < 16) ? sWarp2[lane] : 3.4e38f;
#pragma unroll
        for (int off = 8; off > 0; off >>= 1) {
            float o = __shfl_down_sync(0xffffffffu, v, off);
            v = o < v ? o : v;
        }
        if (lane == 0) sThr = v - DELTA;
    }
    __syncthreads();
    const float thr = sThr;

    // phase 2: compact candidate indices
#pragma unroll
    for (int i = 0; i < 8; ++i) {
        float vv[4] = {q[i].x, q[i].y, q[i].z, q[i].w};
#pragma unroll
        for (int e = 0; e < 4; ++e) {
            if (vv[e] >= thr) {
                unsigned p = atomicAdd(&sCnt, 1u);
                if (p < CAND_CAP) candI[p] = (unsigned)(tid * 32 + i * 4 + e);
            }
        }
    }
    __syncthreads();
    const int C = (int)(sCnt < CAND_CAP ? sCnt : CAND_CAP);

    // phase 3: exact fp32 dot per candidate
    for (int b = 0; b < C; b += 512) {
        int ci = b + tid;
        if (ci < C) {
            const float4* wc = (const float4*)(W + (size_t)candI[ci] * DIM);
            float4 acc4 = make_float4(0.f, 0.f, 0.f, 0.f);
#pragma unroll
            for (int j = 0; j < 32; ++j) {
                float4 a = *((const float4*)sWrow + j);
                float4 bb = __ldg(wc + j);
                acc4.x = fmaf(a.x, bb.x, acc4.x);
                acc4.y = fmaf(a.y, bb.y, acc4.y);
                acc4.z = fmaf(a.z, bb.z, acc4.z);
                acc4.w = fmaf(a.w, bb.w, acc4.w);
            }
            float dot = (acc4.x + acc4.y) + (acc4.z + acc4.w);
            candV[ci] = dot;
            candK[ci] = f2key(dot);
        }
    }
    __syncthreads();

    // phase 4: exact rank (val desc, idx asc)
    for (int b = 0; b < C; b += 512) {
        int ci = b + tid;
        if (ci < C) {
            unsigned myk = candK[ci], myi = candI[ci];
            int rank = 0;
            for (int j = 0; j < C; ++j) {
                unsigned kj = candK[j];
                rank += (kj > myk) || (kj == myk && candI[j] < myi);
            }
            flags[ci] = (rank < TOPK) ? 1u : 0u;
        }
    }
    __syncthreads();

    // phase 5: column-sorted emit
    for (int b = 0; b < C; b += 512) {
        int ci = b + tid;
        if (ci < C && flags[ci]) {
            unsigned myi = candI[ci];
            int pos = 0;
            for (int j = 0; j < C; ++j)
                pos += (flags[j] && candI[j] < myi);
            const long long o = (long long)row * TOPK + pos;
            out[o]             = (float)row;
            out[NKTOT + o]     = (float)myi;
            out[2 * NKTOT + o] = candV[ci];
        }
    }
}

// ---------------- launch ----------------
extern "C" void kernel_launch(void* const* d_in, const int* in_sizes, int n_in,
                              void* d_out, int out_size) {
    const float* W = (const float*)d_in[n_in > 1 ? 1 : 0];
    if (in_sizes[0] == NROWS * DIM) W = (const float*)d_in[0];
    float* out = (float*)d_out;

    cudaFuncSetAttribute(gemm_kernel,
                         cudaFuncAttributeMaxDynamicSharedMemorySize, GEMM_SMEM);

    prep_kernel<<<(NROWS * DIM + 255) / 256, 256>>>(W);
    for (int s = 0; s < NSLABS; ++s) {
        gemm_kernel<<<dim3(NROWS / 128, SLAB / 128), 512, GEMM_SMEM>>>(s * SLAB);
        select_kernel<<<SLAB, 512>>>(W, out, s * SLAB);
    }
}

// round 10
// speedup vs baseline: 1.3907x; 1.0526x over previous
#include <cuda_runtime.h>
#include <cuda_bf16.h>
#include <cstdint>

// Problem constants
constexpr int NROWS = 16384;
constexpr int DIM   = 128;
constexpr int TOPK  = 32;
constexpr int SLAB  = 1024;
constexpr int NSLABS = NROWS / SLAB;          // 16
constexpr long long NKTOT = (long long)NROWS * TOPK;

constexpr int KCAT = 384;                     // 3 x 128 (hi|lo|hi vs hi|hi|lo)
constexpr int NKSTEP = KCAT / 16;             // 24 k-steps

// scratch (sanctioned __device__ globals)
__device__ __align__(128) __nv_bfloat16 g_scratch[(size_t)SLAB * NROWS];      // 32 MB
__device__ __align__(128) __nv_bfloat16 g_Acat[(size_t)NROWS * KCAT];         // 12 MB
__device__ __align__(128) __nv_bfloat16 g_Bcat[(size_t)NROWS * KCAT];         // 12 MB

// ---------------- prep: build split operand tables ----------------
__global__ __launch_bounds__(256) void prep_kernel(const float* __restrict__ W) {
    int t = blockIdx.x * 256 + threadIdx.x;
    if (t >= NROWS * DIM) return;
    int row = t >> 7, j = t & 127;
    float w = W[t];
    __nv_bfloat16 hi = __float2bfloat16(w);
    float r = w - __bfloat162float(hi);
    __nv_bfloat16 lo = __float2bfloat16(r);
    size_t base = (size_t)row * KCAT;
    g_Acat[base + j]       = hi;
    g_Acat[base + 128 + j] = lo;
    g_Acat[base + 256 + j] = hi;
    g_Bcat[base + j]       = hi;
    g_Bcat[base + 128 + j] = hi;
    g_Bcat[base + 256 + j] = lo;
}

// ---------------- HMMA GEMM: 128x128 tile/CTA, K=384 resident, 512 threads ----------------
constexpr int SAC = 392;                      // bf16 per smem row incl pad -> 784 B stride
constexpr int TILE_B = 128 * SAC * 2;         // 100352 B per tile
constexpr int GEMM_SMEM = 2 * TILE_B;         // 200704 -> 1 CTA/SM

__device__ __forceinline__ uint32_t smem_u32(const void* p) {
    uint32_t a;
    asm("{ .reg .u64 t; cvta.to.shared.u64 t, %1; cvt.u32.u64 %0, t; }" : "=r"(a) : "l"(p));
    return a;
}
__device__ __forceinline__ void ldm_x4(uint32_t* r, uint32_t addr) {
    asm volatile("ldmatrix.sync.aligned.m8n8.x4.shared.b16 {%0,%1,%2,%3}, [%4];"
                 : "=r"(r[0]), "=r"(r[1]), "=r"(r[2]), "=r"(r[3]) : "r"(addr));
}
__device__ __forceinline__ void mma16816(float* c, const uint32_t* a, const uint32_t* b) {
    asm volatile(
        "mma.sync.aligned.m16n8k16.row.col.f32.bf16.bf16.f32 "
        "{%0,%1,%2,%3}, {%4,%5,%6,%7}, {%8,%9}, {%0,%1,%2,%3};"
        : "+f"(c[0]), "+f"(c[1]), "+f"(c[2]), "+f"(c[3])
        : "r"(a[0]), "r"(a[1]), "r"(a[2]), "r"(a[3]), "r"(b[0]), "r"(b[1]));
}

__global__ __launch_bounds__(512, 1) void gemm_kernel(int rowBase) {
    extern __shared__ __nv_bfloat16 sm[];
    __nv_bfloat16* As = sm;                   // [128][SAC]
    __nv_bfloat16* Bs = sm + 128 * SAC;

    const int tid  = threadIdx.x;
    const int lane = tid & 31, w = tid >> 5;
    const int wm = w >> 2, wn = w & 3;        // warp grid 4x4, warp tile 32x32
    const int g = lane >> 2, tig = lane & 3;
    const int rowA0 = rowBase + blockIdx.y * 128;
    const int rowB0 = blockIdx.x * 128;

    const uint32_t sbase = smem_u32(sm);
    // ldmatrix lane addresses (validated R7/R8)
    uint32_t addrA[2], addrB[2];
#pragma unroll
    for (int mi = 0; mi < 2; ++mi)
        addrA[mi] = sbase + (uint32_t)((wm * 32 + mi * 16 + (lane & 15)) * 784 + (lane >> 4) * 16);
    const uint32_t grp = lane >> 3;
#pragma unroll
    for (int p = 0; p < 2; ++p)
        addrB[p] = sbase + (uint32_t)TILE_B +
                   (uint32_t)((wn * 32 + p * 16 + (grp >> 1) * 8 + (lane & 7)) * 784 + (grp & 1) * 16);

    // ---- load tiles (coalesced gmem, sequential smem)
    const char* Ag = (const char*)g_Acat + (size_t)rowA0 * 768;
    const char* Bg = (const char*)g_Bcat + (size_t)rowB0 * 768;
#pragma unroll
    for (int it = 0; it < 12; ++it) {
        int i = tid + it * 512;               // 0..6143
        int r = i / 48, c = i % 48;
        uint4 va = *(const uint4*)(Ag + (size_t)r * 768 + c * 16);
        uint4 vb = *(const uint4*)(Bg + (size_t)r * 768 + c * 16);
        *(uint4*)((char*)As + r * 784 + c * 16) = va;
        *(uint4*)((char*)Bs + r * 784 + c * 16) = vb;
    }
    __syncthreads();

    // ---- mainloop: 24 k-steps, double-buffered fragments (prefetch k+1 over k's mma)
    float acc[2][4][4];
#pragma unroll
    for (int mi = 0; mi < 2; ++mi)
#pragma unroll
        for (int ni = 0; ni < 4; ++ni)
#pragma unroll
            for (int e = 0; e < 4; ++e) acc[mi][ni][e] = 0.f;

    uint32_t fA[2][2][4], fB[2][2][4];        // [buf][frag][reg]

#pragma unroll
    for (int mi = 0; mi < 2; ++mi) ldm_x4(fA[0][mi], addrA[mi]);
#pragma unroll
    for (int p = 0; p < 2; ++p)    ldm_x4(fB[0][p],  addrB[p]);

#pragma unroll
    for (int k = 0; k < NKSTEP; ++k) {
        const int cur = k & 1, nxt = cur ^ 1;
        if (k + 1 < NKSTEP) {
            const uint32_t koff = (uint32_t)((k + 1) * 32);
#pragma unroll
            for (int mi = 0; mi < 2; ++mi) ldm_x4(fA[nxt][mi], addrA[mi] + koff);
#pragma unroll
            for (int p = 0; p < 2; ++p)    ldm_x4(fB[nxt][p],  addrB[p] + koff);
        }
#pragma unroll
        for (int mi = 0; mi < 2; ++mi)
#pragma unroll
            for (int ni = 0; ni < 4; ++ni)
                mma16816(acc[mi][ni], fA[cur][mi], fB[cur][ni >> 1] + (ni & 1) * 2);
    }
    __syncthreads();

    // ---- stage accumulators as bf16 (stride 136 bf16), then coalesced copy out
    __nv_bfloat16* st = sm;
#pragma unroll
    for (int mi = 0; mi < 2; ++mi)
#pragma unroll
        for (int ni = 0; ni < 4; ++ni) {
            int r0 = wm * 32 + mi * 16 + g;
            int c0 = wn * 32 + ni * 8 + tig * 2;
            __nv_bfloat162 lo = __float22bfloat162_rn(make_float2(acc[mi][ni][0], acc[mi][ni][1]));
            __nv_bfloat162 hi = __float22bfloat162_rn(make_float2(acc[mi][ni][2], acc[mi][ni][3]));
            *(__nv_bfloat162*)(st + r0 * 136 + c0)       = lo;
            *(__nv_bfloat162*)(st + (r0 + 8) * 136 + c0) = hi;
        }
    __syncthreads();

    __nv_bfloat16* outp = g_scratch + (size_t)(blockIdx.y * 128) * NROWS + rowB0;
#pragma unroll
    for (int it = 0; it < 4; ++it) {
        int i = tid + it * 512;               // 0..2047 (128 rows x 16 uint4)
        int r = i >> 4, c = i & 15;
        uint4 v = *(const uint4*)(st + r * 136 + c * 8);
        *(uint4*)(outp + (size_t)r * NROWS + c * 8) = v;
    }
}

// ---------------- select: pivot prefilter (bf16 approx) + exact fp32 re-rank ----------------
__device__ __forceinline__ unsigned f2key(float f) {
    unsigned u = __float_as_uint(f);
    return u ^ (unsigned)((((int)u) >> 31) | 0x80000000);
}

constexpr int CAND_CAP = 1024;
constexpr float DELTA = 0.15f;   // 2x margin over bf16-scratch (0.065) + split-GEMM (0.012)

__global__ __launch_bounds__(512) void select_kernel(const float* __restrict__ W,
                                                     float* __restrict__ out,
                                                     int rowBase) {
    __shared__ unsigned candI[CAND_CAP];
    __shared__ unsigned candK[CAND_CAP];
    __shared__ float    candV[CAND_CAP];
    __shared__ unsigned flags[CAND_CAP];
    __shared__ float sWrow[128];
    __shared__ float sWarp2[16];
    __shared__ float sThr;
    __shared__ unsigned sCnt;

    const int tid = threadIdx.x;
    const int lane = tid & 31, warp = tid >> 5;
    const int row_local = blockIdx.x;
    const int row = rowBase + row_local;

    if (tid == 0) sCnt = 0;
    if (tid < 32) {
        float4 wv = *((const float4*)(W + (size_t)row * DIM) + tid);
        *((float4*)sWrow + tid) = wv;
    }

    // load 32 contiguous bf16 approx values (4 x uint4 = 64 B)
    const uint4* rp = (const uint4*)(g_scratch + (size_t)row_local * NROWS) + tid * 4;
    uint4 qu[4];
#pragma unroll
    for (int i = 0; i < 4; ++i) qu[i] = rp[i];
    float qv[32];
#pragma unroll
    for (int i = 0; i < 4; ++i) {
        const unsigned wds[4] = {qu[i].x, qu[i].y, qu[i].z, qu[i].w};
#pragma unroll
        for (int j = 0; j < 4; ++j) {
            float2 f = __bfloat1622float2(*(const __nv_bfloat162*)&wds[j]);
            qv[i * 8 + j * 2]     = f.x;
            qv[i * 8 + j * 2 + 1] = f.y;
        }
    }

    // phase 1: per-thread top-2, warp merge, block-min of warp 2nd-max
    float m1 = -3.4e38f, m2 = -3.4e38f;
#pragma unroll
    for (int i = 0; i < 32; ++i) {
        float v = qv[i];
        if (v > m1) { m2 = m1; m1 = v; }
        else if (v > m2) m2 = v;
    }
#pragma unroll
    for (int off = 16; off > 0; off >>= 1) {
        float o1 = __shfl_down_sync(0xffffffffu, m1, off);
        float o2 = __shfl_down_sync(0xffffffffu, m2, off);
        float n1 = m1 > o1 ? m1 : o1;
        float n2 = (m1 > o1) ? (m2 > o1 ? m2 : o1) : (o2 > m1 ? o2 : m1);
        m1 = n1; m2 = n2;
    }
    if (lane == 0) sWarp2[warp] = m2;
    __syncthreads();
    if (warp == 0) {
        float v = (lane < 16) ? sWarp2[lane] : 3.4e38f;
#pragma unroll
        for (int off = 8; off > 0; off >>= 1) {
            float o = __shfl_down_sync(0xffffffffu, v, off);
            v = o < v ? o : v;
        }
        if (lane == 0) sThr = v - DELTA;
    }
    __syncthreads();
    const float thr = sThr;

    // phase 2: compact candidate indices
#pragma unroll
    for (int i = 0; i < 32; ++i) {
        if (qv[i] >= thr) {
            unsigned p = atomicAdd(&sCnt, 1u);
            if (p < CAND_CAP) candI[p] = (unsigned)(tid * 32 + i);
        }
    }
    __syncthreads();
    const int C = (int)(sCnt < CAND_CAP ? sCnt : CAND_CAP);

    // phase 3: exact fp32 dot per candidate
    for (int b = 0; b < C; b += 512) {
        int ci = b + tid;
        if (ci < C) {
            const float4* wc = (const float4*)(W + (size_t)candI[ci] * DIM);
            float4 acc4 = make_float4(0.f, 0.f, 0.f, 0.f);
#pragma unroll
            for (int j = 0; j < 32; ++j) {
                float4 a = *((const float4*)sWrow + j);
                float4 bb = __ldg(wc + j);
                acc4.x = fmaf(a.x, bb.x, acc4.x);
                acc4.y = fmaf(a.y, bb.y, acc4.y);
                acc4.z = fmaf(a.z, bb.z, acc4.z);
                acc4.w = fmaf(a.w, bb.w, acc4.w);
            }
            float dot = (acc4.x + acc4.y) + (acc4.z + acc4.w);
            candV[ci] = dot;
            candK[ci] = f2key(dot);
        }
    }
    __syncthreads();

    // phase 4: exact rank (val desc, idx asc)
    for (int b = 0; b < C; b += 512) {
        int ci = b + tid;
        if (ci < C) {
            unsigned myk = candK[ci], myi = candI[ci];
            int rank = 0;
            for (int j = 0; j < C; ++j) {
                unsigned kj = candK[j];
                rank += (kj > myk) || (kj == myk && candI[j] < myi);
            }
            flags[ci] = (rank < TOPK) ? 1u : 0u;
        }
    }
    __syncthreads();

    // phase 5: column-sorted emit
    for (int b = 0; b < C; b += 512) {
        int ci = b + tid;
        if (ci < C && flags[ci]) {
            unsigned myi = candI[ci];
            int pos = 0;
            for (int j = 0; j < C; ++j)
                pos += (flags[j] && candI[j] < myi);
            const long long o = (long long)row * TOPK + pos;
            out[o]             = (float)row;
            out[NKTOT + o]     = (float)myi;
            out[2 * NKTOT + o] = candV[ci];
        }
    }
}

// ---------------- launch ----------------
extern "C" void kernel_launch(void* const* d_in, const int* in_sizes, int n_in,
                              void* d_out, int out_size) {
    const float* W = (const float*)d_in[n_in > 1 ? 1 : 0];
    if (in_sizes[0] == NROWS * DIM) W = (const float*)d_in[0];
    float* out = (float*)d_out;

    cudaFuncSetAttribute(gemm_kernel,
                         cudaFuncAttributeMaxDynamicSharedMemorySize, GEMM_SMEM);

    prep_kernel<<<(NROWS * DIM + 255) / 256, 256>>>(W);
    for (int s = 0; s < NSLABS; ++s) {
        gemm_kernel<<<dim3(NROWS / 128, SLAB / 128), 512, GEMM_SMEM>>>(s * SLAB);
        select_kernel<<<SLAB, 512>>>(W, out, s * SLAB);
    }
}

// round 12
// speedup vs baseline: 1.9609x; 1.4100x over previous
#include <cuda_runtime.h>
#include <cuda_bf16.h>
#include <cstdint>

// Problem constants
constexpr int NROWS = 16384;
constexpr int DIM   = 128;
constexpr int TOPK  = 32;
constexpr long long NKTOT = (long long)NROWS * TOPK;

constexpr int KCAT = 384;                     // 3 x 128 (hi|lo|hi vs hi|hi|lo)
constexpr int NKSTEP = KCAT / 16;             // 24 k-steps
constexpr int NTILE = NROWS / 128;            // 128 tiles per dim
constexpr int NUPPER = NTILE * (NTILE + 1) / 2;   // 8256 upper-triangle tiles

// scratch (sanctioned __device__ globals)
__device__ __align__(128) __nv_bfloat16 g_scratch[(size_t)NROWS * NROWS];     // 512 MB
__device__ __align__(128) __nv_bfloat16 g_Acat[(size_t)NROWS * KCAT];         // 12 MB
__device__ __align__(128) __nv_bfloat16 g_Bcat[(size_t)NROWS * KCAT];         // 12 MB

// ---------------- prep: build split operand tables ----------------
__global__ __launch_bounds__(256) void prep_kernel(const float* __restrict__ W) {
    int t = blockIdx.x * 256 + threadIdx.x;
    if (t >= NROWS * DIM) return;
    int row = t >> 7, j = t & 127;
    float w = W[t];
    __nv_bfloat16 hi = __float2bfloat16(w);
    float r = w - __bfloat162float(hi);
    __nv_bfloat16 lo = __float2bfloat16(r);
    size_t base = (size_t)row * KCAT;
    g_Acat[base + j]       = hi;
    g_Acat[base + 128 + j] = lo;
    g_Acat[base + 256 + j] = hi;
    g_Bcat[base + j]       = hi;
    g_Bcat[base + 128 + j] = hi;
    g_Bcat[base + 256 + j] = lo;
}

// ---------------- HMMA GEMM: upper-triangle 128x128 tiles, K=384 resident ----------------
constexpr int SAC = 392;                      // bf16 per smem row incl pad -> 784 B stride
constexpr int TILE_B = 128 * SAC * 2;         // 100352 B per tile
constexpr int GEMM_SMEM = 2 * TILE_B;         // 200704 -> 1 CTA/SM

__device__ __forceinline__ uint32_t smem_u32(const void* p) {
    uint32_t a;
    asm("{ .reg .u64 t; cvta.to.shared.u64 t, %1; cvt.u32.u64 %0, t; }" : "=r"(a) : "l"(p));
    return a;
}
__device__ __forceinline__ void ldm_x4(uint32_t* r, uint32_t addr) {
    asm volatile("ldmatrix.sync.aligned.m8n8.x4.shared.b16 {%0,%1,%2,%3}, [%4];"
                 : "=r"(r[0]), "=r"(r[1]), "=r"(r[2]), "=r"(r[3]) : "r"(addr));
}
__device__ __forceinline__ void mma16816(float* c, const uint32_t* a, const uint32_t* b) {
    asm volatile(
        "mma.sync.aligned.m16n8k16.row.col.f32.bf16.bf16.f32 "
        "{%0,%1,%2,%3}, {%4,%5,%6,%7}, {%8,%9}, {%0,%1,%2,%3};"
        : "+f"(c[0]), "+f"(c[1]), "+f"(c[2]), "+f"(c[3])
        : "r"(a[0]), "r"(a[1]), "r"(a[2]), "r"(a[3]), "r"(b[0]), "r"(b[1]));
}

__global__ __launch_bounds__(512, 1) void gemm_kernel() {
    extern __shared__ __nv_bfloat16 sm[];
    __nv_bfloat16* As = sm;                   // [128][SAC]
    __nv_bfloat16* Bs = sm + 128 * SAC;

    // triangular decode: linear tile id -> (ti, tj), tj >= ti
    const int idx = blockIdx.x;
    int ti = 0, off = 0;
    while (off + (NTILE - ti) <= idx) { off += NTILE - ti; ++ti; }
    const int tj = ti + (idx - off);

    const int tid  = threadIdx.x;
    const int lane = tid & 31, w = tid >> 5;
    const int wm = w >> 2, wn = w & 3;        // warp grid 4x4, warp tile 32x32
    const int g = lane >> 2, tig = lane & 3;
    const int rowA0 = ti * 128;               // output rows
    const int rowB0 = tj * 128;               // output cols

    const uint32_t sbase = smem_u32(sm);
    uint32_t addrA[2], addrB[2];
#pragma unroll
    for (int mi = 0; mi < 2; ++mi)
        addrA[mi] = sbase + (uint32_t)((wm * 32 + mi * 16 + (lane & 15)) * 784 + (lane >> 4) * 16);
    const uint32_t grp = lane >> 3;
#pragma unroll
    for (int p = 0; p < 2; ++p)
        addrB[p] = sbase + (uint32_t)TILE_B +
                   (uint32_t)((wn * 32 + p * 16 + (grp >> 1) * 8 + (lane & 7)) * 784 + (grp & 1) * 16);

    // ---- load tiles
    const char* Ag = (const char*)g_Acat + (size_t)rowA0 * 768;
    const char* Bg = (const char*)g_Bcat + (size_t)rowB0 * 768;
#pragma unroll
    for (int it = 0; it < 12; ++it) {
        int i = tid + it * 512;               // 0..6143
        int r = i / 48, c = i % 48;
        uint4 va = *(const uint4*)(Ag + (size_t)r * 768 + c * 16);
        uint4 vb = *(const uint4*)(Bg + (size_t)r * 768 + c * 16);
        *(uint4*)((char*)As + r * 784 + c * 16) = va;
        *(uint4*)((char*)Bs + r * 784 + c * 16) = vb;
    }
    __syncthreads();

    // ---- mainloop: double-buffered fragments
    float acc[2][4][4];
#pragma unroll
    for (int mi = 0; mi < 2; ++mi)
#pragma unroll
        for (int ni = 0; ni < 4; ++ni)
#pragma unroll
            for (int e = 0; e < 4; ++e) acc[mi][ni][e] = 0.f;

    uint32_t fA[2][2][4], fB[2][2][4];
#pragma unroll
    for (int mi = 0; mi < 2; ++mi) ldm_x4(fA[0][mi], addrA[mi]);
#pragma unroll
    for (int p = 0; p < 2; ++p)    ldm_x4(fB[0][p],  addrB[p]);

#pragma unroll
    for (int k = 0; k < NKSTEP; ++k) {
        const int cur = k & 1, nxt = cur ^ 1;
        if (k + 1 < NKSTEP) {
            const uint32_t koff = (uint32_t)((k + 1) * 32);
#pragma unroll
            for (int mi = 0; mi < 2; ++mi) ldm_x4(fA[nxt][mi], addrA[mi] + koff);
#pragma unroll
            for (int p = 0; p < 2; ++p)    ldm_x4(fB[nxt][p],  addrB[p] + koff);
        }
#pragma unroll
        for (int mi = 0; mi < 2; ++mi)
#pragma unroll
            for (int ni = 0; ni < 4; ++ni)
                mma16816(acc[mi][ni], fA[cur][mi], fB[cur][ni >> 1] + (ni & 1) * 2);
    }
    __syncthreads();

    // ---- stage tile as bf16 (stride 136)
    __nv_bfloat16* st = sm;
#pragma unroll
    for (int mi = 0; mi < 2; ++mi)
#pragma unroll
        for (int ni = 0; ni < 4; ++ni) {
            int r0 = wm * 32 + mi * 16 + g;
            int c0 = wn * 32 + ni * 8 + tig * 2;
            __nv_bfloat162 lo = __float22bfloat162_rn(make_float2(acc[mi][ni][0], acc[mi][ni][1]));
            __nv_bfloat162 hi = __float22bfloat162_rn(make_float2(acc[mi][ni][2], acc[mi][ni][3]));
            *(__nv_bfloat162*)(st + r0 * 136 + c0)       = lo;
            *(__nv_bfloat162*)(st + (r0 + 8) * 136 + c0) = hi;
        }
    __syncthreads();

    // ---- normal write: rows rowA0.., cols rowB0.. (coalesced)
    __nv_bfloat16* outp = g_scratch + (size_t)rowA0 * NROWS + rowB0;
#pragma unroll
    for (int it = 0; it < 4; ++it) {
        int i = tid + it * 512;               // 0..2047 (128 rows x 16 uint4)
        int r = i >> 4, c = i & 15;
        uint4 v = *(const uint4*)(st + r * 136 + c * 8);
        *(uint4*)(outp + (size_t)r * NROWS + c * 8) = v;
    }

    // ---- mirror write (tj > ti): M[c][r] = T[r][c] at rows rowB0.., cols rowA0..
    if (tj > ti) {
        __nv_bfloat16* outm = g_scratch + (size_t)rowB0 * NROWS + rowA0;
#pragma unroll
        for (int it = 0; it < 4; ++it) {
            int i = tid + it * 512;           // 0..2047
            int c = i & 127;                  // mirror row (tile col)
            int rch = i >> 7;                 // tile-row chunk (0..15)
            unsigned pk[4];
#pragma unroll
            for (int h = 0; h < 4; ++h) {
                unsigned v0 = *(const unsigned short*)(st + (rch * 8 + 2 * h)     * 136 + c);
                unsigned v1 = *(const unsigned short*)(st + (rch * 8 + 2 * h + 1) * 136 + c);
                pk[h] = v0 | (v1 << 16);
            }
            *(uint4*)(outm + (size_t)c * NROWS + rch * 8) =
                make_uint4(pk[0], pk[1], pk[2], pk[3]);
        }
    }
}

// ---------------- select: pivot prefilter (bf16 approx) + exact fp32 re-rank ----------------
__device__ __forceinline__ unsigned f2key(float f) {
    unsigned u = __float_as_uint(f);
    return u ^ (unsigned)((((int)u) >> 31) | 0x80000000);
}

constexpr int CAND_CAP = 1024;
constexpr float DELTA = 0.15f;   // 2x margin over bf16-scratch (0.065) + split-GEMM (0.012)

__global__ __launch_bounds__(512) void select_kernel(const float* __restrict__ W,
                                                     float* __restrict__ out) {
    __shared__ unsigned candI[CAND_CAP];
    __shared__ unsigned candK[CAND_CAP];
    __shared__ float    candV[CAND_CAP];
    __shared__ unsigned flags[CAND_CAP];
    __shared__ float sWrow[128];
    __shared__ float sWarp2[16];
    __shared__ float sThr;
    __shared__ unsigned sCnt;

    const int tid = threadIdx.x;
    const int lane = tid & 31, warp = tid >> 5;
    const int row = blockIdx.x;

    if (tid == 0) sCnt = 0;
    if (tid < 32) {
        float4 wv = *((const float4*)(W + (size_t)row * DIM) + tid);
        *((float4*)sWrow + tid) = wv;
    }

    // load 32 contiguous bf16 approx values (4 x uint4 = 64 B)
    const uint4* rp = (const uint4*)(g_scratch + (size_t)row * NROWS) + tid * 4;
    uint4 qu[4];
#pragma unroll
    for (int i = 0; i < 4; ++i) qu[i] = rp[i];
    float qv[32];
#pragma unroll
    for (int i = 0; i < 4; ++i) {
        const unsigned wds[4] = {qu[i].x, qu[i].y, qu[i].z, qu[i].w};
#pragma unroll
        for (int j = 0; j < 4; ++j) {
            float2 f = __bfloat1622float2(*(const __nv_bfloat162*)&wds[j]);
            qv[i * 8 + j * 2]     = f.x;
            qv[i * 8 + j * 2 + 1] = f.y;
        }
    }

    // phase 1: per-thread top-2, warp merge, block-min of warp 2nd-max
    float m1 = -3.4e38f, m2 = -3.4e38f;
#pragma unroll
    for (int i = 0; i < 32; ++i) {
        float v = qv[i];
        if (v > m1) { m2 = m1; m1 = v; }
        else if (v > m2) m2 = v;
    }
#pragma unroll
    for (int off = 16; off > 0; off >>= 1) {
        float o1 = __shfl_down_sync(0xffffffffu, m1, off);
        float o2 = __shfl_down_sync(0xffffffffu, m2, off);
        float n1 = m1 > o1 ? m1 : o1;
        float n2 = (m1 > o1) ? (m2 > o1 ? m2 : o1) : (o2 > m1 ? o2 : m1);
        m1 = n1; m2 = n2;
    }
    if (lane == 0) sWarp2[warp] = m2;
    __syncthreads();
    if (warp == 0) {
        float v = (lane < 16) ? sWarp2[lane] : 3.4e38f;
#pragma unroll
        for (int off = 8; off > 0; off >>= 1) {
            float o = __shfl_down_sync(0xffffffffu, v, off);
            v = o < v ? o : v;
        }
        if (lane == 0) sThr = v - DELTA;
    }
    __syncthreads();
    const float thr = sThr;

    // phase 2: compact candidate indices
#pragma unroll
    for (int i = 0; i < 32; ++i) {
        if (qv[i] >= thr) {
            unsigned p = atomicAdd(&sCnt, 1u);
            if (p < CAND_CAP) candI[p] = (unsigned)(tid * 32 + i);
        }
    }
    __syncthreads();
    const int C = (int)(sCnt < CAND_CAP ? sCnt : CAND_CAP);

    // phase 3: exact fp32 dot per candidate
    for (int b = 0; b < C; b += 512) {
        int ci = b + tid;
        if (ci < C) {
            const float4* wc = (const float4*)(W + (size_t)candI[ci] * DIM);
            float4 acc4 = make_float4(0.f, 0.f, 0.f, 0.f);
#pragma unroll
            for (int j = 0; j < 32; ++j) {
                float4 a = *((const float4*)sWrow + j);
                float4 bb = __ldg(wc + j);
                acc4.x = fmaf(a.x, bb.x, acc4.x);
                acc4.y = fmaf(a.y, bb.y, acc4.y);
                acc4.z = fmaf(a.z, bb.z, acc4.z);
                acc4.w = fmaf(a.w, bb.w, acc4.w);
            }
            float dot = (acc4.x + acc4.y) + (acc4.z + acc4.w);
            candV[ci] = dot;
            candK[ci] = f2key(dot);
        }
    }
    __syncthreads();

    // phase 4: exact rank (val desc, idx asc)
    for (int b = 0; b < C; b += 512) {
        int ci = b + tid;
        if (ci < C) {
            unsigned myk = candK[ci], myi = candI[ci];
            int rank = 0;
            for (int j = 0; j < C; ++j) {
                unsigned kj = candK[j];
                rank += (kj > myk) || (kj == myk && candI[j] < myi);
            }
            flags[ci] = (rank < TOPK) ? 1u : 0u;
        }
    }
    __syncthreads();

    // phase 5: column-sorted emit
    for (int b = 0; b < C; b += 512) {
        int ci = b + tid;
        if (ci < C && flags[ci]) {
            unsigned myi = candI[ci];
            int pos = 0;
            for (int j = 0; j < C; ++j)
                pos += (flags[j] && candI[j] < myi);
            const long long o = (long long)row * TOPK + pos;
            out[o]             = (float)row;
            out[NKTOT + o]     = (float)myi;
            out[2 * NKTOT + o] = candV[ci];
        }
    }
}

// ---------------- launch ----------------
extern "C" void kernel_launch(void* const* d_in, const int* in_sizes, int n_in,
                              void* d_out, int out_size) {
    const float* W = (const float*)d_in[n_in > 1 ? 1 : 0];
    if (in_sizes[0] == NROWS * DIM) W = (const float*)d_in[0];
    float* out = (float*)d_out;

    cudaFuncSetAttribute(gemm_kernel,
                         cudaFuncAttributeMaxDynamicSharedMemorySize, GEMM_SMEM);

    prep_kernel<<<(NROWS * DIM + 255) / 256, 256>>>(W);
    gemm_kernel<<<NUPPER, 512, GEMM_SMEM>>>();
    select_kernel<<<NROWS, 512>>>(W, out);
}

// round 16
// speedup vs baseline: 2.0458x; 1.0433x over previous
#include <cuda_runtime.h>
#include <cuda_bf16.h>
#include <cstdint>

// Problem constants
constexpr int NROWS = 16384;
constexpr int DIM   = 128;
constexpr int TOPK  = 32;
constexpr long long NKTOT = (long long)NROWS * TOPK;

constexpr int KCAT = 384;                     // 3 x 128 (hi|lo|hi vs hi|hi|lo)
constexpr int NTILE = NROWS / 128;            // 128 tiles per dim
constexpr int NUPPER = NTILE * (NTILE + 1) / 2;   // 8256 upper-triangle tiles

constexpr int KCH   = 96;                     // K per pipeline chunk
constexpr int NCH   = KCAT / KCH;             // 4 chunks
constexpr int KLS   = KCH / 16;               // 6 k-steps per chunk

// scratch (sanctioned __device__ globals)
__device__ __align__(128) __nv_bfloat16 g_scratch[(size_t)NROWS * NROWS];     // 512 MB
__device__ __align__(128) __nv_bfloat16 g_Acat[(size_t)NROWS * KCAT];         // 12 MB
__device__ __align__(128) __nv_bfloat16 g_Bcat[(size_t)NROWS * KCAT];         // 12 MB

// ---------------- prep: build split operand tables ----------------
__global__ __launch_bounds__(256) void prep_kernel(const float* __restrict__ W) {
    int t = blockIdx.x * 256 + threadIdx.x;
    if (t >= NROWS * DIM) return;
    int row = t >> 7, j = t & 127;
    float w = W[t];
    __nv_bfloat16 hi = __float2bfloat16(w);
    float r = w - __bfloat162float(hi);
    __nv_bfloat16 lo = __float2bfloat16(r);
    size_t base = (size_t)row * KCAT;
    g_Acat[base + j]       = hi;
    g_Acat[base + 128 + j] = lo;
    g_Acat[base + 256 + j] = hi;
    g_Bcat[base + j]       = hi;
    g_Bcat[base + 128 + j] = hi;
    g_Bcat[base + 256 + j] = lo;
}

// ---------------- HMMA GEMM: upper-triangle tiles, cp.async 3-stage K pipeline ----------------
constexpr int ROWB  = 208;                    // smem row stride bytes (96 bf16 + pad)
constexpr int CH_A  = 128 * ROWB;             // 26624 B per operand chunk
constexpr int STAGE = 2 * CH_A;               // 53248 B (A + B)
constexpr int NSTG  = 3;
constexpr int GEMM_SMEM = NSTG * STAGE;       // 159744

__device__ __forceinline__ uint32_t smem_u32(const void* p) {
    uint32_t a;
    asm("{ .reg .u64 t; cvta.to.shared.u64 t, %1; cvt.u32.u64 %0, t; }" : "=r"(a) : "l"(p));
    return a;
}
__device__ __forceinline__ void cp16(uint32_t s, const void* g) {
    asm volatile("cp.async.cg.shared.global [%0], [%1], 16;" :: "r"(s), "l"(g));
}
__device__ __forceinline__ void cp_commit() {
    asm volatile("cp.async.commit_group;" ::: "memory");
}
template <int N>
__device__ __forceinline__ void cp_wait() {
    asm volatile("cp.async.wait_group %0;" :: "n"(N) : "memory");
}
__device__ __forceinline__ void ldm_x4(uint32_t* r, uint32_t addr) {
    asm volatile("ldmatrix.sync.aligned.m8n8.x4.shared.b16 {%0,%1,%2,%3}, [%4];"
                 : "=r"(r[0]), "=r"(r[1]), "=r"(r[2]), "=r"(r[3]) : "r"(addr));
}
__device__ __forceinline__ void mma16816(float* c, const uint32_t* a, const uint32_t* b) {
    asm volatile(
        "mma.sync.aligned.m16n8k16.row.col.f32.bf16.bf16.f32 "
        "{%0,%1,%2,%3}, {%4,%5,%6,%7}, {%8,%9}, {%0,%1,%2,%3};"
        : "+f"(c[0]), "+f"(c[1]), "+f"(c[2]), "+f"(c[3])
        : "r"(a[0]), "r"(a[1]), "r"(a[2]), "r"(a[3]), "r"(b[0]), "r"(b[1]));
}

__global__ __launch_bounds__(512, 1) void gemm_kernel() {
    extern __shared__ char smc[];

    // triangular decode: linear tile id -> (ti, tj), tj >= ti
    const int idx = blockIdx.x;
    int ti = 0, off = 0;
    while (off + (NTILE - ti) <= idx) { off += NTILE - ti; ++ti; }
    const int tj = ti + (idx - off);

    const int tid  = threadIdx.x;
    const int lane = tid & 31, w = tid >> 5;
    const int wm = w >> 2, wn = w & 3;        // warp grid 4x4, warp tile 32x32
    const int g = lane >> 2, tig = lane & 3;
    const int rowA0 = ti * 128;
    const int rowB0 = tj * 128;

    const uint32_t sbase = smem_u32(smc);
    // ldmatrix lane offsets within a stage (A at +0, B at +CH_A)
    uint32_t offA[2], offB[2];
#pragma unroll
    for (int mi = 0; mi < 2; ++mi)
        offA[mi] = (uint32_t)((wm * 32 + mi * 16 + (lane & 15)) * ROWB + (lane >> 4) * 16);
    const uint32_t grp = lane >> 3;
#pragma unroll
    for (int p = 0; p < 2; ++p)
        offB[p] = (uint32_t)CH_A +
                  (uint32_t)((wn * 32 + p * 16 + (grp >> 1) * 8 + (lane & 7)) * ROWB + (grp & 1) * 16);

    const char* Ag = (const char*)g_Acat + (size_t)rowA0 * 768;
    const char* Bg = (const char*)g_Bcat + (size_t)rowB0 * 768;

    // chunk loader: 128 rows x 12 16B-chunks per operand, 512 threads -> 3 iters each
    auto load_chunk = [&](int ch, int stg) {
        const uint32_t sa = sbase + stg * STAGE;
        const int kb = ch * 192;              // chunk byte offset in gmem row
#pragma unroll
        for (int it = 0; it < 3; ++it) {
            int i = tid + it * 512;           // 0..1535
            int r = i / 12, c = i % 12;
            cp16(sa + r * ROWB + c * 16, Ag + (size_t)r * 768 + kb + c * 16);
        }
#pragma unroll
        for (int it = 0; it < 3; ++it) {
            int i = tid + it * 512;
            int r = i / 12, c = i % 12;
            cp16(sa + CH_A + r * ROWB + c * 16, Bg + (size_t)r * 768 + kb + c * 16);
        }
        cp_commit();
    };

    // prologue: chunks 0,1 in flight
    load_chunk(0, 0);
    load_chunk(1, 1);

    float acc[2][4][4];
#pragma unroll
    for (int mi = 0; mi < 2; ++mi)
#pragma unroll
        for (int ni = 0; ni < 4; ++ni)
#pragma unroll
            for (int e = 0; e < 4; ++e) acc[mi][ni][e] = 0.f;

    cp_wait<1>();                             // chunk 0 resident
    __syncthreads();

    uint32_t fA[2][2][4], fB[2][2][4];

#pragma unroll
    for (int ch = 0; ch < NCH; ++ch) {
        const uint32_t stg = sbase + (ch % NSTG) * STAGE;
        // first fragments of this chunk
#pragma unroll
        for (int mi = 0; mi < 2; ++mi) ldm_x4(fA[0][mi], stg + offA[mi]);
#pragma unroll
        for (int p = 0; p < 2; ++p)    ldm_x4(fB[0][p],  stg + offB[p]);

#pragma unroll
        for (int kl = 0; kl < KLS; ++kl) {
            const int cur = kl & 1, nxt = cur ^ 1;
            if (kl + 1 < KLS) {
                const uint32_t koff = (uint32_t)((kl + 1) * 32);
#pragma unroll
                for (int mi = 0; mi < 2; ++mi) ldm_x4(fA[nxt][mi], stg + offA[mi] + koff);
#pragma unroll
                for (int p = 0; p < 2; ++p)    ldm_x4(fB[nxt][p],  stg + offB[p] + koff);
            }
#pragma unroll
            for (int mi = 0; mi < 2; ++mi)
#pragma unroll
                for (int ni = 0; ni < 4; ++ni)
                    mma16816(acc[mi][ni], fA[cur][mi], fB[cur][ni >> 1] + (ni & 1) * 2);
        }

        // pipeline control
        if (ch + 2 < NCH) load_chunk(ch + 2, (ch + 2) % NSTG);
        if (ch + 1 < NCH) {
            if (ch + 2 < NCH) cp_wait<1>(); else cp_wait<0>();
            __syncthreads();
        }
    }
    __syncthreads();

    // ---- stage tile as bf16 (stride 136)
    __nv_bfloat16* st = (__nv_bfloat16*)smc;
#pragma unroll
    for (int mi = 0; mi < 2; ++mi)
#pragma unroll
        for (int ni = 0; ni < 4; ++ni) {
            int r0 = wm * 32 + mi * 16 + g;
            int c0 = wn * 32 + ni * 8 + tig * 2;
            __nv_bfloat162 lo = __float22bfloat162_rn(make_float2(acc[mi][ni][0], acc[mi][ni][1]));
            __nv_bfloat162 hi = __float22bfloat162_rn(make_float2(acc[mi][ni][2], acc[mi][ni][3]));
            *(__nv_bfloat162*)(st + r0 * 136 + c0)       = lo;
            *(__nv_bfloat162*)(st + (r0 + 8) * 136 + c0) = hi;
        }
    __syncthreads();

    // ---- normal write
    __nv_bfloat16* outp = g_scratch + (size_t)rowA0 * NROWS + rowB0;
#pragma unroll
    for (int it = 0; it < 4; ++it) {
        int i = tid + it * 512;               // 0..2047
        int r = i >> 4, c = i & 15;
        uint4 v = *(const uint4*)(st + r * 136 + c * 8);
        *(uint4*)(outp + (size_t)r * NROWS + c * 8) = v;
    }

    // ---- mirror write (tj > ti)
    if (tj > ti) {
        __nv_bfloat16* outm = g_scratch + (size_t)rowB0 * NROWS + rowA0;
#pragma unroll
        for (int it = 0; it < 4; ++it) {
            int i = tid + it * 512;
            int c = i & 127;
            int rch = i >> 7;
            unsigned pk[4];
#pragma unroll
            for (int h = 0; h < 4; ++h) {
                unsigned v0 = *(const unsigned short*)(st + (rch * 8 + 2 * h)     * 136 + c);
                unsigned v1 = *(const unsigned short*)(st + (rch * 8 + 2 * h + 1) * 136 + c);
                pk[h] = v0 | (v1 << 16);
            }
            *(uint4*)(outm + (size_t)c * NROWS + rch * 8) =
                make_uint4(pk[0], pk[1], pk[2], pk[3]);
        }
    }
}

// ---------------- select: pivot prefilter (bf16 approx) + exact fp32 re-rank ----------------
__device__ __forceinline__ unsigned f2key(float f) {
    unsigned u = __float_as_uint(f);
    return u ^ (unsigned)((((int)u) >> 31) | 0x80000000);
}

constexpr int CAND_CAP = 1024;
constexpr float DELTA = 0.15f;   // 2x margin over bf16-scratch (0.065) + split-GEMM (0.012)

__global__ __launch_bounds__(512) void select_kernel(const float* __restrict__ W,
                                                     float* __restrict__ out) {
    __shared__ unsigned candI[CAND_CAP];
    __shared__ unsigned candK[CAND_CAP];
    __shared__ float    candV[CAND_CAP];
    __shared__ unsigned flags[CAND_CAP];
    __shared__ float sWrow[128];
    __shared__ float sWarp2[16];
    __shared__ float sThr;
    __shared__ unsigned sCnt;

    const int tid = threadIdx.x;
    const int lane = tid & 31, warp = tid >> 5;
    const int row = blockIdx.x;

    if (tid == 0) sCnt = 0;
    if (tid < 32) {
        float4 wv = *((const float4*)(W + (size_t)row * DIM) + tid);
        *((float4*)sWrow + tid) = wv;
    }

    const uint4* rp = (const uint4*)(g_scratch + (size_t)row * NROWS) + tid * 4;
    uint4 qu[4];
#pragma unroll
    for (int i = 0; i < 4; ++i) qu[i] = rp[i];
    float qv[32];
#pragma unroll
    for (int i = 0; i < 4; ++i) {
        const unsigned wds[4] = {qu[i].x, qu[i].y, qu[i].z, qu[i].w};
#pragma unroll
        for (int j = 0; j < 4; ++j) {
            float2 f = __bfloat1622float2(*(const __nv_bfloat162*)&wds[j]);
            qv[i * 8 + j * 2]     = f.x;
            qv[i * 8 + j * 2 + 1] = f.y;
        }
    }

    // phase 1: per-thread top-2, warp merge, block-min of warp 2nd-max
    float m1 = -3.4e38f, m2 = -3.4e38f;
#pragma unroll
    for (int i = 0; i < 32; ++i) {
        float v = qv[i];
        if (v > m1) { m2 = m1; m1 = v; }
        else if (v > m2) m2 = v;
    }
#pragma unroll
    for (int off = 16; off > 0; off >>= 1) {
        float o1 = __shfl_down_sync(0xffffffffu, m1, off);
        float o2 = __shfl_down_sync(0xffffffffu, m2, off);
        float n1 = m1 > o1 ? m1 : o1;
        float n2 = (m1 > o1) ? (m2 > o1 ? m2 : o1) : (o2 > m1 ? o2 : m1);
        m1 = n1; m2 = n2;
    }
    if (lane == 0) sWarp2[warp] = m2;
    __syncthreads();
    if (warp == 0) {
        float v = (lane < 16) ? sWarp2[lane] : 3.4e38f;
#pragma unroll
        for (int off = 8; off > 0; off >>= 1) {
            float o = __shfl_down_sync(0xffffffffu, v, off);
            v = o < v ? o : v;
        }
        if (lane == 0) sThr = v - DELTA;
    }
    __syncthreads();
    const float thr = sThr;

    // phase 2: compact candidate indices
#pragma unroll
    for (int i = 0; i < 32; ++i) {
        if (qv[i] >= thr) {
            unsigned p = atomicAdd(&sCnt, 1u);
            if (p < CAND_CAP) candI[p] = (unsigned)(tid * 32 + i);
        }
    }
    __syncthreads();
    const int C = (int)(sCnt < CAND_CAP ? sCnt : CAND_CAP);

    // phase 3: exact fp32 dot per candidate
    for (int b = 0; b < C; b += 512) {
        int ci = b + tid;
        if (ci < C) {
            const float4* wc = (const float4*)(W + (size_t)candI[ci] * DIM);
            float4 acc4 = make_float4(0.f, 0.f, 0.f, 0.f);
#pragma unroll
            for (int j = 0; j < 32; ++j) {
                float4 a = *((const float4*)sWrow + j);
                float4 bb = __ldg(wc + j);
                acc4.x = fmaf(a.x, bb.x, acc4.x);
                acc4.y = fmaf(a.y, bb.y, acc4.y);
                acc4.z = fmaf(a.z, bb.z, acc4.z);
                acc4.w = fmaf(a.w, bb.w, acc4.w);
            }
            float dot = (acc4.x + acc4.y) + (acc4.z + acc4.w);
            candV[ci] = dot;
            candK[ci] = f2key(dot);
        }
    }
    __syncthreads();

    // phase 4: exact rank (val desc, idx asc)
    for (int b = 0; b < C; b += 512) {
        int ci = b + tid;
        if (ci < C) {
            unsigned myk = candK[ci], myi = candI[ci];
            int rank = 0;
            for (int j = 0; j < C; ++j) {
                unsigned kj = candK[j];
                rank += (kj > myk) || (kj == myk && candI[j] < myi);
            }
            flags[ci] = (rank < TOPK) ? 1u : 0u;
        }
    }
    __syncthreads();

    // phase 5: column-sorted emit
    for (int b = 0; b < C; b += 512) {
        int ci = b + tid;
        if (ci < C && flags[ci]) {
            unsigned myi = candI[ci];
            int pos = 0;
            for (int j = 0; j < C; ++j)
                pos += (flags[j] && candI[j] < myi);
            const long long o = (long long)row * TOPK + pos;
            out[o]             = (float)row;
            out[NKTOT + o]     = (float)myi;
            out[2 * NKTOT + o] = candV[ci];
        }
    }
}

// ---------------- launch ----------------
extern "C" void kernel_launch(void* const* d_in, const int* in_sizes, int n_in,
                              void* d_out, int out_size) {
    const float* W = (const float*)d_in[n_in > 1 ? 1 : 0];
    if (in_sizes[0] == NROWS * DIM) W = (const float*)d_in[0];
    float* out = (float*)d_out;

    cudaFuncSetAttribute(gemm_kernel,
                         cudaFuncAttributeMaxDynamicSharedMemorySize, GEMM_SMEM);

    prep_kernel<<<(NROWS * DIM + 255) / 256, 256>>>(W);
    gemm_kernel<<<NUPPER, 512, GEMM_SMEM>>>();
    select_kernel<<<NROWS, 512>>>(W, out);
}